// round 1
// baseline (speedup 1.0000x reference)
#include <cuda_runtime.h>

#define Bz 4
#define Tz 1024
#define Dz 1024
#define Hz 16
#define DHz 64
#define Mz (Bz*Tz)        // 4096
#define Kz Dz
#define Nz Dz
#define MD (Mz*Dz)        // 4,194,304

// scratch: 0..3 = xr,xk,xv,xw ; 4=r(sigmoid) ; 5=k ; 6=v ; 7=exp(w) ; 8=o
__device__ float g_buf[9][MD];

// ---------------------------------------------------------------------------
// token-shift mix: x_mixed = tm*x + (1-tm)*x_prev   (float4 vectorized)
// ---------------------------------------------------------------------------
__global__ void __launch_bounds__(256) mix_kernel(
    const float4* __restrict__ x,
    const float4* __restrict__ tmr, const float4* __restrict__ tmk,
    const float4* __restrict__ tmv, const float4* __restrict__ tmw)
{
    int idx = blockIdx.x * blockDim.x + threadIdx.x;   // over MD/4
    int m  = idx >> 8;            // D/4 = 256 float4 per row
    int c4 = idx & 255;
    int t  = m & (Tz - 1);

    float4 xc = x[idx];
    float4 xp = make_float4(0.f, 0.f, 0.f, 0.f);
    if (t != 0) xp = x[idx - 256];

    float4 w, o;
    #define DO_MIX(TMV, DSTI)                                   \
        w = TMV[c4];                                            \
        o.x = w.x * xc.x + (1.f - w.x) * xp.x;                  \
        o.y = w.y * xc.y + (1.f - w.y) * xp.y;                  \
        o.z = w.z * xc.z + (1.f - w.z) * xp.z;                  \
        o.w = w.w * xc.w + (1.f - w.w) * xp.w;                  \
        reinterpret_cast<float4*>(g_buf[DSTI])[idx] = o;
    DO_MIX(tmr, 0)
    DO_MIX(tmk, 1)
    DO_MIX(tmv, 2)
    DO_MIX(tmw, 3)
    #undef DO_MIX
}

// ---------------------------------------------------------------------------
// SGEMM: C[m][n] = sum_k A[m][k] * W[n][k]    (A: M x K, W: N x K, both row-major)
// 128x128 block tile, BK=16, 8x8 per thread, 256 threads.
// EPI: 0 identity, 1 sigmoid, 2 sigmoid * exp(-1e-4)
// ---------------------------------------------------------------------------
template<int EPI>
__device__ __forceinline__ float epi_f(float v)
{
    if (EPI == 1) return 1.f / (1.f + __expf(-v));
    if (EPI == 2) return 0.999900004999833f / (1.f + __expf(-v));
    return v;
}

template<int EPI, int SRC, int DST>
__global__ void __launch_bounds__(256) sgemm_k(const float* __restrict__ W,
                                               float* __restrict__ Cout)
{
    const int BM = 128, BN = 128, BK = 16;
    __shared__ float As[BK][BM + 4];
    __shared__ float Bs[BK][BN + 4];

    const float* __restrict__ A = g_buf[SRC];
    float* C = (DST >= 0) ? g_buf[(DST >= 0) ? DST : 0] : Cout;

    int tid = threadIdx.x;
    int bm = blockIdx.y * BM;
    int bn = blockIdx.x * BN;

    int ar = tid >> 2;            // 0..63
    int ac = (tid & 3) << 2;      // 0,4,8,12
    int tx = tid & 15, ty = tid >> 4;

    float acc[8][8];
    #pragma unroll
    for (int i = 0; i < 8; i++)
        #pragma unroll
        for (int j = 0; j < 8; j++) acc[i][j] = 0.f;

    const float* Aptr = A + (size_t)(bm + ar) * Kz + ac;
    const float* Wptr = W + (size_t)(bn + ar) * Kz + ac;

    for (int k0 = 0; k0 < Kz; k0 += BK) {
        float4 a0 = *(const float4*)(Aptr + k0);
        float4 a1 = *(const float4*)(Aptr + 64 * Kz + k0);
        float4 b0 = *(const float4*)(Wptr + k0);
        float4 b1 = *(const float4*)(Wptr + 64 * Kz + k0);

        if (k0) __syncthreads();

        As[ac + 0][ar]      = a0.x; As[ac + 1][ar]      = a0.y;
        As[ac + 2][ar]      = a0.z; As[ac + 3][ar]      = a0.w;
        As[ac + 0][ar + 64] = a1.x; As[ac + 1][ar + 64] = a1.y;
        As[ac + 2][ar + 64] = a1.z; As[ac + 3][ar + 64] = a1.w;
        Bs[ac + 0][ar]      = b0.x; Bs[ac + 1][ar]      = b0.y;
        Bs[ac + 2][ar]      = b0.z; Bs[ac + 3][ar]      = b0.w;
        Bs[ac + 0][ar + 64] = b1.x; Bs[ac + 1][ar + 64] = b1.y;
        Bs[ac + 2][ar + 64] = b1.z; Bs[ac + 3][ar + 64] = b1.w;
        __syncthreads();

        #pragma unroll
        for (int kk = 0; kk < BK; kk++) {
            float af[8], bf[8];
            *(float4*)&af[0] = *(const float4*)&As[kk][ty * 8];
            *(float4*)&af[4] = *(const float4*)&As[kk][ty * 8 + 4];
            *(float4*)&bf[0] = *(const float4*)&Bs[kk][tx * 8];
            *(float4*)&bf[4] = *(const float4*)&Bs[kk][tx * 8 + 4];
            #pragma unroll
            for (int i = 0; i < 8; i++)
                #pragma unroll
                for (int j = 0; j < 8; j++)
                    acc[i][j] += af[i] * bf[j];
        }
    }

    #pragma unroll
    for (int i = 0; i < 8; i++) {
        int row = bm + ty * 8 + i;
        #pragma unroll
        for (int j = 0; j < 8; j += 4) {
            float4 v;
            v.x = epi_f<EPI>(acc[i][j + 0]);
            v.y = epi_f<EPI>(acc[i][j + 1]);
            v.z = epi_f<EPI>(acc[i][j + 2]);
            v.w = epi_f<EPI>(acc[i][j + 3]);
            *(float4*)&C[(size_t)row * Nz + bn + tx * 8 + j] = v;
        }
    }
}

// ---------------------------------------------------------------------------
// Recurrent scan: one block per (b,h); thread tid owns state column j=tid
// (64 fp32 regs). o[j] = sum_i r[i]*s[i][j] + c*v[j],  c = sum_i r[i]*e^(u+k)_i
// s[i][j] = ew[i]*s[i][j] + k[i]*v[j]. Double-buffered smem vector staging
// with next-step global prefetch.
// ---------------------------------------------------------------------------
__global__ void __launch_bounds__(64) scan_kernel(const float* __restrict__ u)
{
    __shared__ float s_r[2][64], s_k[2][64], s_v[2][64], s_e[2][64];
    __shared__ float s_part[2][2];

    int tid  = threadIdx.x;
    int lane = tid & 31, wid = tid >> 5;
    int bh = blockIdx.x;
    int b = bh >> 4, h = bh & 15;

    float u_val = u[h * 64 + tid];
    const float* __restrict__ gr = g_buf[4];
    const float* __restrict__ gk = g_buf[5];
    const float* __restrict__ gv = g_buf[6];
    const float* __restrict__ ge = g_buf[7];
    float* __restrict__ go = g_buf[8];

    int base = (b * Tz) * Dz + h * 64 + tid;

    float s[64];
    #pragma unroll
    for (int i = 0; i < 64; i++) s[i] = 0.f;

    s_r[0][tid] = gr[base]; s_k[0][tid] = gk[base];
    s_v[0][tid] = gv[base]; s_e[0][tid] = ge[base];
    __syncthreads();

    for (int t = 0; t < Tz; t++) {
        int cur = t & 1, nxt = cur ^ 1;

        // prefetch t+1 vectors into registers (latency overlapped with compute)
        float pr = 0.f, pk = 0.f, pv = 0.f, pe = 0.f;
        if (t + 1 < Tz) {
            int nb = base + (t + 1) * Dz;
            pr = gr[nb]; pk = gk[nb]; pv = gv[nb]; pe = ge[nb];
        }

        // scalar bonus coefficient c
        float term = s_r[cur][tid] * __expf(u_val + s_k[cur][tid]);
        #pragma unroll
        for (int off = 16; off > 0; off >>= 1)
            term += __shfl_xor_sync(0xffffffffu, term, off);
        if (lane == 0) s_part[cur][wid] = term;
        __syncthreads();
        float c = s_part[cur][0] + s_part[cur][1];

        float vj = s_v[cur][tid];
        float o0 = 0.f, o1 = 0.f, o2 = 0.f, o3 = 0.f;
        #pragma unroll
        for (int i = 0; i < 64; i += 4) {
            float r0 = s_r[cur][i],     e0 = s_e[cur][i],     k0 = s_k[cur][i];
            o0 += r0 * s[i];     s[i]     = e0 * s[i]     + k0 * vj;
            float r1 = s_r[cur][i + 1], e1 = s_e[cur][i + 1], k1 = s_k[cur][i + 1];
            o1 += r1 * s[i + 1]; s[i + 1] = e1 * s[i + 1] + k1 * vj;
            float r2 = s_r[cur][i + 2], e2 = s_e[cur][i + 2], k2 = s_k[cur][i + 2];
            o2 += r2 * s[i + 2]; s[i + 2] = e2 * s[i + 2] + k2 * vj;
            float r3 = s_r[cur][i + 3], e3 = s_e[cur][i + 3], k3 = s_k[cur][i + 3];
            o3 += r3 * s[i + 3]; s[i + 3] = e3 * s[i + 3] + k3 * vj;
        }
        go[base + t * Dz] = ((o0 + o1) + (o2 + o3)) + c * vj;

        s_r[nxt][tid] = pr; s_k[nxt][tid] = pk;
        s_v[nxt][tid] = pv; s_e[nxt][tid] = pe;
        __syncthreads();
    }
}

// ---------------------------------------------------------------------------
// GroupNorm over head dim (64) + multiply by r. One warp per group, in-place.
// ---------------------------------------------------------------------------
__global__ void __launch_bounds__(256) gnorm_kernel(const float* __restrict__ ln_w,
                                                    const float* __restrict__ ln_b)
{
    int warp = (blockIdx.x * blockDim.x + threadIdx.x) >> 5;
    int lane = threadIdx.x & 31;
    if (warp >= Bz * Tz * Hz) return;

    int base = warp * 64;
    float a0 = g_buf[8][base + lane];
    float a1 = g_buf[8][base + 32 + lane];

    float sum = a0 + a1;
    float sq  = a0 * a0 + a1 * a1;
    #pragma unroll
    for (int off = 16; off > 0; off >>= 1) {
        sum += __shfl_xor_sync(0xffffffffu, sum, off);
        sq  += __shfl_xor_sync(0xffffffffu, sq,  off);
    }
    float mean = sum * (1.f / 64.f);
    float var  = sq * (1.f / 64.f) - mean * mean;
    float rs   = rsqrtf(var + 1e-5f);

    float r0 = g_buf[4][base + lane];
    float r1 = g_buf[4][base + 32 + lane];
    g_buf[8][base + lane]      = ((a0 - mean) * rs * ln_w[lane]      + ln_b[lane])      * r0;
    g_buf[8][base + 32 + lane] = ((a1 - mean) * rs * ln_w[lane + 32] + ln_b[lane + 32]) * r1;
}

// ---------------------------------------------------------------------------
extern "C" void kernel_launch(void* const* d_in, const int* in_sizes, int n_in,
                              void* d_out, int out_size)
{
    const float* x    = (const float*)d_in[0];
    const float* W_r  = (const float*)d_in[1];
    const float* W_k  = (const float*)d_in[2];
    const float* W_v  = (const float*)d_in[3];
    const float* W_w  = (const float*)d_in[4];
    const float* W_o  = (const float*)d_in[5];
    const float* u    = (const float*)d_in[6];
    const float* tm_r = (const float*)d_in[7];
    const float* tm_k = (const float*)d_in[8];
    const float* tm_v = (const float*)d_in[9];
    const float* tm_w = (const float*)d_in[10];
    const float* ln_w = (const float*)d_in[11];
    const float* ln_b = (const float*)d_in[12];
    float* out = (float*)d_out;

    mix_kernel<<<(MD / 4) / 256, 256>>>(
        (const float4*)x, (const float4*)tm_r, (const float4*)tm_k,
        (const float4*)tm_v, (const float4*)tm_w);

    dim3 gg(Nz / 128, Mz / 128);   // (8, 32)
    sgemm_k<1, 0, 4><<<gg, 256>>>(W_r, nullptr);   // r  = sigmoid(xr @ W_r^T)
    sgemm_k<0, 1, 5><<<gg, 256>>>(W_k, nullptr);   // k
    sgemm_k<0, 2, 6><<<gg, 256>>>(W_v, nullptr);   // v
    sgemm_k<2, 3, 7><<<gg, 256>>>(W_w, nullptr);   // exp(w) = sigmoid(z)*e^-1e-4

    scan_kernel<<<Bz * Hz, 64>>>(u);

    gnorm_kernel<<<(Bz * Tz * Hz) / 8, 256>>>(ln_w, ln_b);

    sgemm_k<0, 8, -1><<<gg, 256>>>(W_o, out);      // out = o @ W_o^T
}

// round 2
// speedup vs baseline: 1.3471x; 1.3471x over previous
#include <cuda_runtime.h>
#include <cstdint>

#define Bz 4
#define Tz 1024
#define Dz 1024
#define Hz 16
#define DHz 64
#define Mz (Bz*Tz)        // 4096
#define Kz Dz
#define Nz Dz
#define MD (Mz*Dz)        // 4,194,304

// scratch: 0..3 = xr,xk,xv,xw ; 4=r(sigmoid) ; 5=k ; 6=v ; 7=exp(w) ; 8=o
__device__ float g_buf[9][MD];

// ---------------------------------------------------------------------------
// token-shift mix: x_mixed = tm*x + (1-tm)*x_prev   (float4 vectorized)
// ---------------------------------------------------------------------------
__global__ void __launch_bounds__(256) mix_kernel(
    const float4* __restrict__ x,
    const float4* __restrict__ tmr, const float4* __restrict__ tmk,
    const float4* __restrict__ tmv, const float4* __restrict__ tmw)
{
    int idx = blockIdx.x * blockDim.x + threadIdx.x;   // over MD/4
    int m  = idx >> 8;            // D/4 = 256 float4 per row
    int c4 = idx & 255;
    int t  = m & (Tz - 1);

    float4 xc = x[idx];
    float4 xp = make_float4(0.f, 0.f, 0.f, 0.f);
    if (t != 0) xp = x[idx - 256];

    float4 w, o;
    #define DO_MIX(TMV, DSTI)                                   \
        w = TMV[c4];                                            \
        o.x = w.x * xc.x + (1.f - w.x) * xp.x;                  \
        o.y = w.y * xc.y + (1.f - w.y) * xp.y;                  \
        o.z = w.z * xc.z + (1.f - w.z) * xp.z;                  \
        o.w = w.w * xc.w + (1.f - w.w) * xp.w;                  \
        reinterpret_cast<float4*>(g_buf[DSTI])[idx] = o;
    DO_MIX(tmr, 0)
    DO_MIX(tmk, 1)
    DO_MIX(tmv, 2)
    DO_MIX(tmw, 3)
    #undef DO_MIX
}

// ---------------------------------------------------------------------------
// tf32 tensor-core GEMM: C[m][n] = sum_k A[m][k] * W[n][k]
// 128x128 tile, BK=16, 8 warps (2x4), warp tile 64x32, m16n8k8 tf32 MMA.
// Operands rounded to tf32 with cvt.rna at staging (unbiased).
// EPI: 0 identity, 1 sigmoid, 2 sigmoid * exp(-1e-4)
// ---------------------------------------------------------------------------
template<int EPI>
__device__ __forceinline__ float epi_f(float v)
{
    if (EPI == 1) return 1.f / (1.f + __expf(-v));
    if (EPI == 2) return 0.999900004999833f / (1.f + __expf(-v));
    return v;
}

__device__ __forceinline__ float to_tf32(float x)
{
    uint32_t d;
    asm("cvt.rna.tf32.f32 %0, %1;" : "=r"(d) : "f"(x));
    return __uint_as_float(d);
}

__device__ __forceinline__ void mma_tf32(float c[4], const uint32_t a[4],
                                         const uint32_t b[2])
{
    asm volatile(
        "mma.sync.aligned.m16n8k8.row.col.f32.tf32.tf32.f32 "
        "{%0,%1,%2,%3}, {%4,%5,%6,%7}, {%8,%9}, {%0,%1,%2,%3};"
        : "+f"(c[0]), "+f"(c[1]), "+f"(c[2]), "+f"(c[3])
        : "r"(a[0]), "r"(a[1]), "r"(a[2]), "r"(a[3]),
          "r"(b[0]), "r"(b[1]));
}

#define SLD 20   // BK(16) + pad(4): conflict-free fragment loads

template<int EPI, int SRC, int DST>
__global__ void __launch_bounds__(256) sgemm_k(const float* __restrict__ W,
                                               float* __restrict__ Cout)
{
    const int BM = 128, BK = 16;
    __shared__ __align__(16) float As[2][BM * SLD];
    __shared__ __align__(16) float Bs[2][BM * SLD];

    const float* __restrict__ A = g_buf[SRC];
    float* C = (DST >= 0) ? g_buf[(DST >= 0) ? DST : 0] : Cout;

    int tid  = threadIdx.x;
    int lane = tid & 31;
    int wid  = tid >> 5;
    int bm = blockIdx.y * BM;
    int bn = blockIdx.x * BM;

    int wm = (wid >> 2) * 64;       // 0 / 64
    int wn = (wid & 3) * 32;        // 0 / 32 / 64 / 96
    int frow = lane >> 2;           // 0..7
    int fk   = lane & 3;            // 0..3

    int ar = tid >> 2;              // 0..63 (staging row)
    int ac = (tid & 3) << 2;        // 0,4,8,12 (staging k-col)

    const float* Aptr = A + (size_t)(bm + ar) * Kz + ac;
    const float* Wptr = W + (size_t)(bn + ar) * Kz + ac;

    float acc[4][4][4];
    #pragma unroll
    for (int i = 0; i < 4; i++)
        #pragma unroll
        for (int j = 0; j < 4; j++)
            #pragma unroll
            for (int r = 0; r < 4; r++) acc[i][j][r] = 0.f;

    #define STAGE(S, A0, A1, B0, B1)                                         \
    {                                                                        \
        float4 ta;                                                           \
        ta.x = to_tf32((A0).x); ta.y = to_tf32((A0).y);                      \
        ta.z = to_tf32((A0).z); ta.w = to_tf32((A0).w);                      \
        *(float4*)&As[S][ar * SLD + ac] = ta;                                \
        ta.x = to_tf32((A1).x); ta.y = to_tf32((A1).y);                      \
        ta.z = to_tf32((A1).z); ta.w = to_tf32((A1).w);                      \
        *(float4*)&As[S][(ar + 64) * SLD + ac] = ta;                         \
        ta.x = to_tf32((B0).x); ta.y = to_tf32((B0).y);                      \
        ta.z = to_tf32((B0).z); ta.w = to_tf32((B0).w);                      \
        *(float4*)&Bs[S][ar * SLD + ac] = ta;                                \
        ta.x = to_tf32((B1).x); ta.y = to_tf32((B1).y);                      \
        ta.z = to_tf32((B1).z); ta.w = to_tf32((B1).w);                      \
        *(float4*)&Bs[S][(ar + 64) * SLD + ac] = ta;                         \
    }

    // prologue: stage k0 = 0 into buffer 0
    {
        float4 a0 = *(const float4*)(Aptr);
        float4 a1 = *(const float4*)(Aptr + 64 * Kz);
        float4 b0 = *(const float4*)(Wptr);
        float4 b1 = *(const float4*)(Wptr + 64 * Kz);
        STAGE(0, a0, a1, b0, b1)
    }
    __syncthreads();

    int s = 0;
    for (int k0 = 0; k0 < Kz; k0 += BK) {
        bool more = (k0 + BK) < Kz;
        float4 a0, a1, b0, b1;
        if (more) {
            a0 = *(const float4*)(Aptr + k0 + BK);
            a1 = *(const float4*)(Aptr + 64 * Kz + k0 + BK);
            b0 = *(const float4*)(Wptr + k0 + BK);
            b1 = *(const float4*)(Wptr + 64 * Kz + k0 + BK);
        }

        // compute on buffer s
        #pragma unroll
        for (int ks = 0; ks < 2; ks++) {
            int ko = ks * 8;
            uint32_t afr[4][4], bfr[4][2];
            #pragma unroll
            for (int mt = 0; mt < 4; mt++) {
                const float* p = &As[s][(wm + mt * 16 + frow) * SLD + ko + fk];
                afr[mt][0] = __float_as_uint(p[0]);
                afr[mt][1] = __float_as_uint(p[8 * SLD]);
                afr[mt][2] = __float_as_uint(p[4]);
                afr[mt][3] = __float_as_uint(p[8 * SLD + 4]);
            }
            #pragma unroll
            for (int nt = 0; nt < 4; nt++) {
                const float* q = &Bs[s][(wn + nt * 8 + frow) * SLD + ko + fk];
                bfr[nt][0] = __float_as_uint(q[0]);
                bfr[nt][1] = __float_as_uint(q[4]);
            }
            #pragma unroll
            for (int mt = 0; mt < 4; mt++)
                #pragma unroll
                for (int nt = 0; nt < 4; nt++)
                    mma_tf32(acc[mt][nt], afr[mt], bfr[nt]);
        }

        if (more) STAGE(s ^ 1, a0, a1, b0, b1)
        __syncthreads();
        s ^= 1;
    }
    #undef STAGE

    // epilogue: c0:(row,col) c1:(row,col+1) c2:(row+8,col) c3:(row+8,col+1)
    #pragma unroll
    for (int mt = 0; mt < 4; mt++) {
        int row = bm + wm + mt * 16 + frow;
        #pragma unroll
        for (int nt = 0; nt < 4; nt++) {
            int col = bn + wn + nt * 8 + fk * 2;
            float2 v0, v1;
            v0.x = epi_f<EPI>(acc[mt][nt][0]);
            v0.y = epi_f<EPI>(acc[mt][nt][1]);
            v1.x = epi_f<EPI>(acc[mt][nt][2]);
            v1.y = epi_f<EPI>(acc[mt][nt][3]);
            *(float2*)&C[(size_t)row * Nz + col]       = v0;
            *(float2*)&C[(size_t)(row + 8) * Nz + col] = v1;
        }
    }
}

// ---------------------------------------------------------------------------
// Recurrent scan: one block of 128 threads per (b,h).
// thread (j = tid&63, half = tid>>6) owns state rows [half*32, half*32+32)
// of column j. o[j] = sum_i r[i]*s[i][j] + c*v[j], c = sum_i r[i]*e^(u+k)_i.
// Partials combined through smem at the step sync.
// ---------------------------------------------------------------------------
__global__ void __launch_bounds__(128) scan_kernel(const float* __restrict__ u)
{
    __shared__ __align__(16) float s_r[2][64], s_k[2][64], s_v[2][64], s_e[2][64];
    __shared__ float s_opart[64];
    __shared__ float s_cpart[2][2];

    int tid  = threadIdx.x;
    int lane = tid & 31;
    int j    = tid & 63;
    int half = tid >> 6;
    int bh = blockIdx.x;
    int b = bh >> 4, h = bh & 15;

    float u_val = u[h * 64 + j];          // used by half 0 (i = j there)
    const float* __restrict__ gr = g_buf[4];
    const float* __restrict__ gk = g_buf[5];
    const float* __restrict__ gv = g_buf[6];
    const float* __restrict__ ge = g_buf[7];
    float* __restrict__ go = g_buf[8];

    int base = (b * Tz) * Dz + h * 64 + j;

    float s[32];
    #pragma unroll
    for (int i = 0; i < 32; i++) s[i] = 0.f;

    // stage t = 0: half0 loads r,k ; half1 loads v,e
    if (half == 0) { s_r[0][j] = gr[base]; s_k[0][j] = gk[base]; }
    else           { s_v[0][j] = gv[base]; s_e[0][j] = ge[base]; }
    __syncthreads();

    for (int t = 0; t < Tz; t++) {
        int cur = t & 1, nxt = cur ^ 1;

        // prefetch t+1 vectors into regs
        float p0 = 0.f, p1 = 0.f;
        if (t + 1 < Tz) {
            int nb = base + (t + 1) * Dz;
            if (half == 0) { p0 = gr[nb]; p1 = gk[nb]; }
            else           { p0 = gv[nb]; p1 = ge[nb]; }
        }

        // bonus coefficient c (computed by half 0: warps 0,1; i = j)
        if (half == 0) {
            float term = s_r[cur][j] * __expf(u_val + s_k[cur][j]);
            #pragma unroll
            for (int off = 16; off > 0; off >>= 1)
                term += __shfl_xor_sync(0xffffffffu, term, off);
            if (lane == 0) s_cpart[cur][tid >> 5] = term;
        }

        // inner: 32 state rows, staged vectors as float4 broadcasts
        float vj = s_v[cur][j];
        const float4* r4 = (const float4*)&s_r[cur][half * 32];
        const float4* e4 = (const float4*)&s_e[cur][half * 32];
        const float4* k4 = (const float4*)&s_k[cur][half * 32];
        float o0 = 0.f, o1 = 0.f, o2 = 0.f, o3 = 0.f;
        #pragma unroll
        for (int q = 0; q < 8; q++) {
            float4 rv = r4[q], ev = e4[q], kv = k4[q];
            o0 += rv.x * s[q * 4 + 0]; s[q * 4 + 0] = ev.x * s[q * 4 + 0] + kv.x * vj;
            o1 += rv.y * s[q * 4 + 1]; s[q * 4 + 1] = ev.y * s[q * 4 + 1] + kv.y * vj;
            o2 += rv.z * s[q * 4 + 2]; s[q * 4 + 2] = ev.z * s[q * 4 + 2] + kv.z * vj;
            o3 += rv.w * s[q * 4 + 3]; s[q * 4 + 3] = ev.w * s[q * 4 + 3] + kv.w * vj;
        }
        float o_part = (o0 + o1) + (o2 + o3);

        if (half == 1) s_opart[j] = o_part;
        __syncthreads();

        if (half == 0) {
            float c = s_cpart[cur][0] + s_cpart[cur][1];
            go[base + t * Dz] = o_part + s_opart[j] + c * vj;
        }

        // stage t+1
        if (half == 0) { s_r[nxt][j] = p0; s_k[nxt][j] = p1; }
        else           { s_v[nxt][j] = p0; s_e[nxt][j] = p1; }
        __syncthreads();
    }
}

// ---------------------------------------------------------------------------
// GroupNorm over head dim (64) + multiply by r. One warp per group, in-place.
// ---------------------------------------------------------------------------
__global__ void __launch_bounds__(256) gnorm_kernel(const float* __restrict__ ln_w,
                                                    const float* __restrict__ ln_b)
{
    int warp = (blockIdx.x * blockDim.x + threadIdx.x) >> 5;
    int lane = threadIdx.x & 31;
    if (warp >= Bz * Tz * Hz) return;

    int base = warp * 64;
    float a0 = g_buf[8][base + lane];
    float a1 = g_buf[8][base + 32 + lane];

    float sum = a0 + a1;
    float sq  = a0 * a0 + a1 * a1;
    #pragma unroll
    for (int off = 16; off > 0; off >>= 1) {
        sum += __shfl_xor_sync(0xffffffffu, sum, off);
        sq  += __shfl_xor_sync(0xffffffffu, sq,  off);
    }
    float mean = sum * (1.f / 64.f);
    float var  = sq * (1.f / 64.f) - mean * mean;
    float rs   = rsqrtf(var + 1e-5f);

    float r0 = g_buf[4][base + lane];
    float r1 = g_buf[4][base + 32 + lane];
    g_buf[8][base + lane]      = ((a0 - mean) * rs * ln_w[lane]      + ln_b[lane])      * r0;
    g_buf[8][base + 32 + lane] = ((a1 - mean) * rs * ln_w[lane + 32] + ln_b[lane + 32]) * r1;
}

// ---------------------------------------------------------------------------
extern "C" void kernel_launch(void* const* d_in, const int* in_sizes, int n_in,
                              void* d_out, int out_size)
{
    const float* x    = (const float*)d_in[0];
    const float* W_r  = (const float*)d_in[1];
    const float* W_k  = (const float*)d_in[2];
    const float* W_v  = (const float*)d_in[3];
    const float* W_w  = (const float*)d_in[4];
    const float* W_o  = (const float*)d_in[5];
    const float* u    = (const float*)d_in[6];
    const float* tm_r = (const float*)d_in[7];
    const float* tm_k = (const float*)d_in[8];
    const float* tm_v = (const float*)d_in[9];
    const float* tm_w = (const float*)d_in[10];
    const float* ln_w = (const float*)d_in[11];
    const float* ln_b = (const float*)d_in[12];
    float* out = (float*)d_out;

    mix_kernel<<<(MD / 4) / 256, 256>>>(
        (const float4*)x, (const float4*)tm_r, (const float4*)tm_k,
        (const float4*)tm_v, (const float4*)tm_w);

    dim3 gg(Nz / 128, Mz / 128);   // (8, 32)
    sgemm_k<1, 0, 4><<<gg, 256>>>(W_r, nullptr);   // r  = sigmoid(xr @ W_r^T)
    sgemm_k<0, 1, 5><<<gg, 256>>>(W_k, nullptr);   // k
    sgemm_k<0, 2, 6><<<gg, 256>>>(W_v, nullptr);   // v
    sgemm_k<2, 3, 7><<<gg, 256>>>(W_w, nullptr);   // exp(w) = sigmoid(z)*e^-1e-4

    scan_kernel<<<Bz * Hz, 128>>>(u);

    gnorm_kernel<<<(Bz * Tz * Hz) / 8, 256>>>(ln_w, ln_b);

    sgemm_k<0, 8, -1><<<gg, 256>>>(W_o, out);      // out = o @ W_o^T
}

// round 3
// speedup vs baseline: 2.2429x; 1.6649x over previous
#include <cuda_runtime.h>
#include <cstdint>

#define Bz 4
#define Tz 1024
#define Dz 1024
#define Hz 16
#define DHz 64
#define Mz (Bz*Tz)        // 4096
#define Kz Dz
#define Nz Dz
#define MD (Mz*Dz)        // 4,194,304
#define NBH (Bz*Hz)       // 64
#define CL 64             // chunk length
#define NC (Tz/CL)        // 16 chunks

// scratch: 0..3 = xr,xk,xv,xw ; 4=r(sigmoid) ; 5=k ; 6=v ; 7=exp(w) ; 8=o
__device__ float g_buf[9][MD];
// chunked-scan scratch
__device__ float g_state[NBH * NC * DHz * DHz];   // 16.8 MB: S_local then S_init
__device__ float g_wprod[NBH * NC * DHz];         // per-chunk decay products
__device__ float g_bsum[Bz * Tz * Hz];            // bonus coefficients

// ---------------------------------------------------------------------------
// token-shift mix: x_mixed = tm*x + (1-tm)*x_prev   (float4 vectorized)
// ---------------------------------------------------------------------------
__global__ void __launch_bounds__(256) mix_kernel(
    const float4* __restrict__ x,
    const float4* __restrict__ tmr, const float4* __restrict__ tmk,
    const float4* __restrict__ tmv, const float4* __restrict__ tmw)
{
    int idx = blockIdx.x * blockDim.x + threadIdx.x;   // over MD/4
    int m  = idx >> 8;            // D/4 = 256 float4 per row
    int c4 = idx & 255;
    int t  = m & (Tz - 1);

    float4 xc = x[idx];
    float4 xp = make_float4(0.f, 0.f, 0.f, 0.f);
    if (t != 0) xp = x[idx - 256];

    float4 w, o;
    #define DO_MIX(TMV, DSTI)                                   \
        w = TMV[c4];                                            \
        o.x = w.x * xc.x + (1.f - w.x) * xp.x;                  \
        o.y = w.y * xc.y + (1.f - w.y) * xp.y;                  \
        o.z = w.z * xc.z + (1.f - w.z) * xp.z;                  \
        o.w = w.w * xc.w + (1.f - w.w) * xp.w;                  \
        reinterpret_cast<float4*>(g_buf[DSTI])[idx] = o;
    DO_MIX(tmr, 0)
    DO_MIX(tmk, 1)
    DO_MIX(tmv, 2)
    DO_MIX(tmw, 3)
    #undef DO_MIX
}

// ---------------------------------------------------------------------------
// tf32 tensor-core GEMM (same as round 2)
// ---------------------------------------------------------------------------
template<int EPI>
__device__ __forceinline__ float epi_f(float v)
{
    if (EPI == 1) return 1.f / (1.f + __expf(-v));
    if (EPI == 2) return 0.999900004999833f / (1.f + __expf(-v));
    return v;
}

__device__ __forceinline__ float to_tf32(float x)
{
    uint32_t d;
    asm("cvt.rna.tf32.f32 %0, %1;" : "=r"(d) : "f"(x));
    return __uint_as_float(d);
}

__device__ __forceinline__ void mma_tf32(float c[4], const uint32_t a[4],
                                         const uint32_t b[2])
{
    asm volatile(
        "mma.sync.aligned.m16n8k8.row.col.f32.tf32.tf32.f32 "
        "{%0,%1,%2,%3}, {%4,%5,%6,%7}, {%8,%9}, {%0,%1,%2,%3};"
        : "+f"(c[0]), "+f"(c[1]), "+f"(c[2]), "+f"(c[3])
        : "r"(a[0]), "r"(a[1]), "r"(a[2]), "r"(a[3]),
          "r"(b[0]), "r"(b[1]));
}

#define SLD 20   // BK(16) + pad(4)

template<int EPI, int SRC, int DST>
__global__ void __launch_bounds__(256) sgemm_k(const float* __restrict__ W,
                                               float* __restrict__ Cout)
{
    const int BM = 128, BK = 16;
    __shared__ __align__(16) float As[2][BM * SLD];
    __shared__ __align__(16) float Bs[2][BM * SLD];

    const float* __restrict__ A = g_buf[SRC];
    float* C = (DST >= 0) ? g_buf[(DST >= 0) ? DST : 0] : Cout;

    int tid  = threadIdx.x;
    int lane = tid & 31;
    int wid  = tid >> 5;
    int bm = blockIdx.y * BM;
    int bn = blockIdx.x * BM;

    int wm = (wid >> 2) * 64;
    int wn = (wid & 3) * 32;
    int frow = lane >> 2;
    int fk   = lane & 3;

    int ar = tid >> 2;
    int ac = (tid & 3) << 2;

    const float* Aptr = A + (size_t)(bm + ar) * Kz + ac;
    const float* Wptr = W + (size_t)(bn + ar) * Kz + ac;

    float acc[4][4][4];
    #pragma unroll
    for (int i = 0; i < 4; i++)
        #pragma unroll
        for (int j = 0; j < 4; j++)
            #pragma unroll
            for (int r = 0; r < 4; r++) acc[i][j][r] = 0.f;

    #define STAGE(S, A0, A1, B0, B1)                                         \
    {                                                                        \
        float4 ta;                                                           \
        ta.x = to_tf32((A0).x); ta.y = to_tf32((A0).y);                      \
        ta.z = to_tf32((A0).z); ta.w = to_tf32((A0).w);                      \
        *(float4*)&As[S][ar * SLD + ac] = ta;                                \
        ta.x = to_tf32((A1).x); ta.y = to_tf32((A1).y);                      \
        ta.z = to_tf32((A1).z); ta.w = to_tf32((A1).w);                      \
        *(float4*)&As[S][(ar + 64) * SLD + ac] = ta;                         \
        ta.x = to_tf32((B0).x); ta.y = to_tf32((B0).y);                      \
        ta.z = to_tf32((B0).z); ta.w = to_tf32((B0).w);                      \
        *(float4*)&Bs[S][ar * SLD + ac] = ta;                                \
        ta.x = to_tf32((B1).x); ta.y = to_tf32((B1).y);                      \
        ta.z = to_tf32((B1).z); ta.w = to_tf32((B1).w);                      \
        *(float4*)&Bs[S][(ar + 64) * SLD + ac] = ta;                         \
    }

    {
        float4 a0 = *(const float4*)(Aptr);
        float4 a1 = *(const float4*)(Aptr + 64 * Kz);
        float4 b0 = *(const float4*)(Wptr);
        float4 b1 = *(const float4*)(Wptr + 64 * Kz);
        STAGE(0, a0, a1, b0, b1)
    }
    __syncthreads();

    int s = 0;
    for (int k0 = 0; k0 < Kz; k0 += BK) {
        bool more = (k0 + BK) < Kz;
        float4 a0, a1, b0, b1;
        if (more) {
            a0 = *(const float4*)(Aptr + k0 + BK);
            a1 = *(const float4*)(Aptr + 64 * Kz + k0 + BK);
            b0 = *(const float4*)(Wptr + k0 + BK);
            b1 = *(const float4*)(Wptr + 64 * Kz + k0 + BK);
        }

        #pragma unroll
        for (int ks = 0; ks < 2; ks++) {
            int ko = ks * 8;
            uint32_t afr[4][4], bfr[4][2];
            #pragma unroll
            for (int mt = 0; mt < 4; mt++) {
                const float* p = &As[s][(wm + mt * 16 + frow) * SLD + ko + fk];
                afr[mt][0] = __float_as_uint(p[0]);
                afr[mt][1] = __float_as_uint(p[8 * SLD]);
                afr[mt][2] = __float_as_uint(p[4]);
                afr[mt][3] = __float_as_uint(p[8 * SLD + 4]);
            }
            #pragma unroll
            for (int nt = 0; nt < 4; nt++) {
                const float* q = &Bs[s][(wn + nt * 8 + frow) * SLD + ko + fk];
                bfr[nt][0] = __float_as_uint(q[0]);
                bfr[nt][1] = __float_as_uint(q[4]);
            }
            #pragma unroll
            for (int mt = 0; mt < 4; mt++)
                #pragma unroll
                for (int nt = 0; nt < 4; nt++)
                    mma_tf32(acc[mt][nt], afr[mt], bfr[nt]);
        }

        if (more) STAGE(s ^ 1, a0, a1, b0, b1)
        __syncthreads();
        s ^= 1;
    }
    #undef STAGE

    #pragma unroll
    for (int mt = 0; mt < 4; mt++) {
        int row = bm + wm + mt * 16 + frow;
        #pragma unroll
        for (int nt = 0; nt < 4; nt++) {
            int col = bn + wn + nt * 8 + fk * 2;
            float2 v0, v1;
            v0.x = epi_f<EPI>(acc[mt][nt][0]);
            v0.y = epi_f<EPI>(acc[mt][nt][1]);
            v1.x = epi_f<EPI>(acc[mt][nt][2]);
            v1.y = epi_f<EPI>(acc[mt][nt][3]);
            *(float2*)&C[(size_t)row * Nz + col]       = v0;
            *(float2*)&C[(size_t)(row + 8) * Nz + col] = v1;
        }
    }
}

// ---------------------------------------------------------------------------
// bonus coefficients: g_bsum[b,t,h] = sum_i r[i] * exp(u[i]+k[i])
// one warp per (b,t,h)
// ---------------------------------------------------------------------------
__global__ void __launch_bounds__(256) bonus_kernel(const float* __restrict__ u)
{
    int warp = (blockIdx.x * blockDim.x + threadIdx.x) >> 5;
    int lane = threadIdx.x & 31;
    if (warp >= Bz * Tz * Hz) return;
    int bt = warp / Hz;           // b*Tz + t
    int h  = warp - bt * Hz;

    int base = bt * Dz + h * 64;
    float r0 = g_buf[4][base + lane];
    float r1 = g_buf[4][base + 32 + lane];
    float k0 = g_buf[5][base + lane];
    float k1 = g_buf[5][base + 32 + lane];
    float u0 = u[h * 64 + lane];
    float u1 = u[h * 64 + 32 + lane];

    float term = r0 * __expf(u0 + k0) + r1 * __expf(u1 + k1);
    #pragma unroll
    for (int off = 16; off > 0; off >>= 1)
        term += __shfl_xor_sync(0xffffffffu, term, off);
    if (lane == 0) g_bsum[warp] = term;
}

// ---------------------------------------------------------------------------
// Pass A: chunk-local scan (zero init). grid (NC-1, NBH), 64 threads.
// Thread j owns state column j. Writes S_local_c and per-channel decay prod.
// ---------------------------------------------------------------------------
__global__ void __launch_bounds__(64) scanA_kernel()
{
    __shared__ __align__(16) float s_k[2][64], s_e[2][64];

    int j  = threadIdx.x;
    int c  = blockIdx.x;          // 0..NC-2
    int bh = blockIdx.y;
    int b = bh >> 4, h = bh & 15;

    const float* __restrict__ gk = g_buf[5];
    const float* __restrict__ gv = g_buf[6];
    const float* __restrict__ ge = g_buf[7];

    int base = (b * Tz + c * CL) * Dz + h * 64 + j;

    float s[64];
    #pragma unroll
    for (int i = 0; i < 64; i++) s[i] = 0.f;

    // prologue t=0
    float cv = gv[base], ce = ge[base];
    s_k[0][j] = gk[base];
    s_e[0][j] = ce;
    __syncthreads();

    float wp = 1.f;
    for (int t = 0; t < CL; t++) {
        int cur = t & 1, nxt = cur ^ 1;

        float nk = 0.f, ne = 0.f, nv = 0.f;
        if (t + 1 < CL) {
            int nb = base + (t + 1) * Dz;
            nk = gk[nb]; ne = ge[nb]; nv = gv[nb];
        }

        float vj = cv;
        const float4* k4 = (const float4*)&s_k[cur][0];
        const float4* e4 = (const float4*)&s_e[cur][0];
        #pragma unroll
        for (int q = 0; q < 16; q++) {
            float4 kv = k4[q], ev = e4[q];
            s[q * 4 + 0] = ev.x * s[q * 4 + 0] + kv.x * vj;
            s[q * 4 + 1] = ev.y * s[q * 4 + 1] + kv.y * vj;
            s[q * 4 + 2] = ev.z * s[q * 4 + 2] + kv.z * vj;
            s[q * 4 + 3] = ev.w * s[q * 4 + 3] + kv.w * vj;
        }
        wp *= ce;

        s_k[nxt][j] = nk; s_e[nxt][j] = ne;
        cv = nv; ce = ne;
        __syncthreads();
    }

    int slot = (bh * NC + c) * DHz;
    #pragma unroll 8
    for (int i = 0; i < 64; i++)
        g_state[(size_t)(slot + i) * DHz + j] = s[i];
    g_wprod[slot + j] = wp;
}

// ---------------------------------------------------------------------------
// Pass B: sequential prefix over chunks. grid NBH, 64 threads.
// In-place: slot c becomes S_init_c (state before chunk c).
// ---------------------------------------------------------------------------
__global__ void __launch_bounds__(64) scanB_kernel()
{
    __shared__ float s_w[64];
    int j  = threadIdx.x;
    int bh = blockIdx.x;

    float R[64];
    #pragma unroll
    for (int i = 0; i < 64; i++) R[i] = 0.f;

    for (int c = 0; c < NC; c++) {
        int slot = (bh * NC + c) * DHz;
        if (c < NC - 1) {
            s_w[j] = g_wprod[slot + j];
            __syncthreads();
            #pragma unroll 8
            for (int i = 0; i < 64; i++) {
                size_t a = (size_t)(slot + i) * DHz + j;
                float local = g_state[a];
                g_state[a] = R[i];
                R[i] = s_w[i] * R[i] + local;
            }
            __syncthreads();
        } else {
            #pragma unroll 8
            for (int i = 0; i < 64; i++)
                g_state[(size_t)(slot + i) * DHz + j] = R[i];
        }
    }
}

// ---------------------------------------------------------------------------
// Pass C: outputs. grid (NC, NBH), 64 threads. Start from S_init_c.
// o_t[j] = sum_i r[i] s[i][j] + bsum_t * v_t[j]; then state update.
// ---------------------------------------------------------------------------
__global__ void __launch_bounds__(64) scanC_kernel()
{
    __shared__ __align__(16) float s_r[2][64], s_k[2][64], s_e[2][64];

    int j  = threadIdx.x;
    int c  = blockIdx.x;
    int bh = blockIdx.y;
    int b = bh >> 4, h = bh & 15;

    const float* __restrict__ gr = g_buf[4];
    const float* __restrict__ gk = g_buf[5];
    const float* __restrict__ gv = g_buf[6];
    const float* __restrict__ ge = g_buf[7];
    float* __restrict__ go = g_buf[8];

    int base  = (b * Tz + c * CL) * Dz + h * 64 + j;
    int bbase = (b * Tz + c * CL) * Hz + h;

    float s[64];
    {
        int slot = (bh * NC + c) * DHz;
        #pragma unroll 8
        for (int i = 0; i < 64; i++)
            s[i] = g_state[(size_t)(slot + i) * DHz + j];
    }

    float cv = gv[base];
    float cb = g_bsum[bbase];
    s_r[0][j] = gr[base];
    s_k[0][j] = gk[base];
    s_e[0][j] = ge[base];
    __syncthreads();

    for (int t = 0; t < CL; t++) {
        int cur = t & 1, nxt = cur ^ 1;

        float nr = 0.f, nk = 0.f, ne = 0.f, nv = 0.f, nb = 0.f;
        if (t + 1 < CL) {
            int g = base + (t + 1) * Dz;
            nr = gr[g]; nk = gk[g]; ne = ge[g]; nv = gv[g];
            nb = g_bsum[bbase + (t + 1) * Hz];
        }

        float vj = cv;
        const float4* r4 = (const float4*)&s_r[cur][0];
        const float4* k4 = (const float4*)&s_k[cur][0];
        const float4* e4 = (const float4*)&s_e[cur][0];
        float o0 = 0.f, o1 = 0.f, o2 = 0.f, o3 = 0.f;
        #pragma unroll
        for (int q = 0; q < 16; q++) {
            float4 rv = r4[q], kv = k4[q], ev = e4[q];
            o0 += rv.x * s[q * 4 + 0]; s[q * 4 + 0] = ev.x * s[q * 4 + 0] + kv.x * vj;
            o1 += rv.y * s[q * 4 + 1]; s[q * 4 + 1] = ev.y * s[q * 4 + 1] + kv.y * vj;
            o2 += rv.z * s[q * 4 + 2]; s[q * 4 + 2] = ev.z * s[q * 4 + 2] + kv.z * vj;
            o3 += rv.w * s[q * 4 + 3]; s[q * 4 + 3] = ev.w * s[q * 4 + 3] + kv.w * vj;
        }
        go[base + t * Dz] = ((o0 + o1) + (o2 + o3)) + cb * vj;

        s_r[nxt][j] = nr; s_k[nxt][j] = nk; s_e[nxt][j] = ne;
        cv = nv; cb = nb;
        __syncthreads();
    }
}

// ---------------------------------------------------------------------------
// GroupNorm over head dim (64) + multiply by r. One warp per group, in-place.
// ---------------------------------------------------------------------------
__global__ void __launch_bounds__(256) gnorm_kernel(const float* __restrict__ ln_w,
                                                    const float* __restrict__ ln_b)
{
    int warp = (blockIdx.x * blockDim.x + threadIdx.x) >> 5;
    int lane = threadIdx.x & 31;
    if (warp >= Bz * Tz * Hz) return;

    int base = warp * 64;
    float a0 = g_buf[8][base + lane];
    float a1 = g_buf[8][base + 32 + lane];

    float sum = a0 + a1;
    float sq  = a0 * a0 + a1 * a1;
    #pragma unroll
    for (int off = 16; off > 0; off >>= 1) {
        sum += __shfl_xor_sync(0xffffffffu, sum, off);
        sq  += __shfl_xor_sync(0xffffffffu, sq,  off);
    }
    float mean = sum * (1.f / 64.f);
    float var  = sq * (1.f / 64.f) - mean * mean;
    float rs   = rsqrtf(var + 1e-5f);

    float r0 = g_buf[4][base + lane];
    float r1 = g_buf[4][base + 32 + lane];
    g_buf[8][base + lane]      = ((a0 - mean) * rs * ln_w[lane]      + ln_b[lane])      * r0;
    g_buf[8][base + 32 + lane] = ((a1 - mean) * rs * ln_w[lane + 32] + ln_b[lane + 32]) * r1;
}

// ---------------------------------------------------------------------------
extern "C" void kernel_launch(void* const* d_in, const int* in_sizes, int n_in,
                              void* d_out, int out_size)
{
    const float* x    = (const float*)d_in[0];
    const float* W_r  = (const float*)d_in[1];
    const float* W_k  = (const float*)d_in[2];
    const float* W_v  = (const float*)d_in[3];
    const float* W_w  = (const float*)d_in[4];
    const float* W_o  = (const float*)d_in[5];
    const float* u    = (const float*)d_in[6];
    const float* tm_r = (const float*)d_in[7];
    const float* tm_k = (const float*)d_in[8];
    const float* tm_v = (const float*)d_in[9];
    const float* tm_w = (const float*)d_in[10];
    const float* ln_w = (const float*)d_in[11];
    const float* ln_b = (const float*)d_in[12];
    float* out = (float*)d_out;

    mix_kernel<<<(MD / 4) / 256, 256>>>(
        (const float4*)x, (const float4*)tm_r, (const float4*)tm_k,
        (const float4*)tm_v, (const float4*)tm_w);

    dim3 gg(Nz / 128, Mz / 128);   // (8, 32)
    sgemm_k<1, 0, 4><<<gg, 256>>>(W_r, nullptr);   // r  = sigmoid(xr @ W_r^T)
    sgemm_k<0, 1, 5><<<gg, 256>>>(W_k, nullptr);   // k
    sgemm_k<0, 2, 6><<<gg, 256>>>(W_v, nullptr);   // v
    sgemm_k<2, 3, 7><<<gg, 256>>>(W_w, nullptr);   // exp(w) = sigmoid(z)*e^-1e-4

    bonus_kernel<<<(Bz * Tz * Hz) / 8, 256>>>(u);

    scanA_kernel<<<dim3(NC - 1, NBH), 64>>>();
    scanB_kernel<<<NBH, 64>>>();
    scanC_kernel<<<dim3(NC, NBH), 64>>>();

    gnorm_kernel<<<(Bz * Tz * Hz) / 8, 256>>>(ln_w, ln_b);

    sgemm_k<0, 8, -1><<<gg, 256>>>(W_o, out);      // out = o @ W_o^T
}

// round 4
// speedup vs baseline: 2.9880x; 1.3322x over previous
#include <cuda_runtime.h>
#include <cstdint>

#define Bz 4
#define Tz 1024
#define Dz 1024
#define Hz 16
#define DHz 64
#define Mz (Bz*Tz)        // 4096
#define Kz Dz
#define Nz Dz
#define MD (Mz*Dz)        // 4,194,304
#define NBH (Bz*Hz)       // 64
#define CL 64             // chunk length
#define NC (Tz/CL)        // 16 chunks

// scratch: 0..3 = xr,xk,xv,xw (tf32-rounded) ; 4=r ; 5=k ; 6=v ; 7=exp(w) ; 8=o
__device__ float g_buf[9][MD];
__device__ float g_wr[5 * Dz * Dz];               // tf32-rounded weights
__device__ float g_state[NBH * NC * DHz * DHz];   // chunk states
__device__ float g_wprod[NBH * NC * DHz];         // per-chunk decay products
__device__ float g_bsum[Bz * Tz * Hz];            // bonus coefficients

__device__ __forceinline__ float to_tf32(float x)
{
    uint32_t d;
    asm("cvt.rna.tf32.f32 %0, %1;" : "=r"(d) : "f"(x));
    return __uint_as_float(d);
}

// ---------------------------------------------------------------------------
// round the 5 weight matrices to tf32 into g_wr
// ---------------------------------------------------------------------------
__global__ void __launch_bounds__(256) roundw_kernel(
    const float4* __restrict__ a, const float4* __restrict__ b,
    const float4* __restrict__ c, const float4* __restrict__ d,
    const float4* __restrict__ e)
{
    int idx = blockIdx.x * 256 + threadIdx.x;      // 0 .. 5*262144-1
    int which = idx >> 18;
    int off = idx & 262143;
    const float4* src = which == 0 ? a : which == 1 ? b : which == 2 ? c
                       : which == 3 ? d : e;
    float4 v = src[off];
    v.x = to_tf32(v.x); v.y = to_tf32(v.y); v.z = to_tf32(v.z); v.w = to_tf32(v.w);
    reinterpret_cast<float4*>(g_wr)[idx] = v;
}

// ---------------------------------------------------------------------------
// token-shift mix, outputs tf32-rounded (GEMM inputs only)
// ---------------------------------------------------------------------------
__global__ void __launch_bounds__(256) mix_kernel(
    const float4* __restrict__ x,
    const float4* __restrict__ tmr, const float4* __restrict__ tmk,
    const float4* __restrict__ tmv, const float4* __restrict__ tmw)
{
    int idx = blockIdx.x * blockDim.x + threadIdx.x;   // over MD/4
    int m  = idx >> 8;
    int c4 = idx & 255;
    int t  = m & (Tz - 1);

    float4 xc = x[idx];
    float4 xp = make_float4(0.f, 0.f, 0.f, 0.f);
    if (t != 0) xp = x[idx - 256];

    float4 w, o;
    #define DO_MIX(TMV, DSTI)                                   \
        w = TMV[c4];                                            \
        o.x = to_tf32(w.x * xc.x + (1.f - w.x) * xp.x);         \
        o.y = to_tf32(w.y * xc.y + (1.f - w.y) * xp.y);         \
        o.z = to_tf32(w.z * xc.z + (1.f - w.z) * xp.z);         \
        o.w = to_tf32(w.w * xc.w + (1.f - w.w) * xp.w);         \
        reinterpret_cast<float4*>(g_buf[DSTI])[idx] = o;
    DO_MIX(tmr, 0)
    DO_MIX(tmk, 1)
    DO_MIX(tmv, 2)
    DO_MIX(tmw, 3)
    #undef DO_MIX
}

// ---------------------------------------------------------------------------
// tf32 tensor-core GEMM body (inputs pre-rounded; no cvt in loop)
// epi: 0 identity, 1 sigmoid, 2 sigmoid * exp(-1e-4)
// ---------------------------------------------------------------------------
__device__ __forceinline__ void mma_tf32(float c[4], const uint32_t a[4],
                                         const uint32_t b[2])
{
    asm volatile(
        "mma.sync.aligned.m16n8k8.row.col.f32.tf32.tf32.f32 "
        "{%0,%1,%2,%3}, {%4,%5,%6,%7}, {%8,%9}, {%0,%1,%2,%3};"
        : "+f"(c[0]), "+f"(c[1]), "+f"(c[2]), "+f"(c[3])
        : "r"(a[0]), "r"(a[1]), "r"(a[2]), "r"(a[3]),
          "r"(b[0]), "r"(b[1]));
}

#define SLD 20   // BK(16) + pad(4)

__device__ __forceinline__ void gemm_body(
    float* __restrict__ As, float* __restrict__ Bs,   // each [2][128*SLD]
    const float* __restrict__ A, const float* __restrict__ W,
    float* __restrict__ C, int epi)
{
    const int BK = 16;
    const int BUF = 128 * SLD;

    int tid  = threadIdx.x;
    int lane = tid & 31;
    int wid  = tid >> 5;
    int bm = blockIdx.y * 128;
    int bn = blockIdx.x * 128;

    int wm = (wid >> 2) * 64;
    int wn = (wid & 3) * 32;
    int frow = lane >> 2;
    int fk   = lane & 3;

    int ar = tid >> 2;
    int ac = (tid & 3) << 2;

    const float* Aptr = A + (size_t)(bm + ar) * Kz + ac;
    const float* Wptr = W + (size_t)(bn + ar) * Kz + ac;

    float acc[4][4][4];
    #pragma unroll
    for (int i = 0; i < 4; i++)
        #pragma unroll
        for (int j = 0; j < 4; j++)
            #pragma unroll
            for (int r = 0; r < 4; r++) acc[i][j][r] = 0.f;

    #define STAGE(S, A0, A1, B0, B1)                                 \
        *(float4*)&As[(S) * BUF + ar * SLD + ac] = A0;                \
        *(float4*)&As[(S) * BUF + (ar + 64) * SLD + ac] = A1;         \
        *(float4*)&Bs[(S) * BUF + ar * SLD + ac] = B0;                \
        *(float4*)&Bs[(S) * BUF + (ar + 64) * SLD + ac] = B1;

    {
        float4 a0 = *(const float4*)(Aptr);
        float4 a1 = *(const float4*)(Aptr + 64 * Kz);
        float4 b0 = *(const float4*)(Wptr);
        float4 b1 = *(const float4*)(Wptr + 64 * Kz);
        STAGE(0, a0, a1, b0, b1)
    }
    __syncthreads();

    int s = 0;
    for (int k0 = 0; k0 < Kz; k0 += BK) {
        bool more = (k0 + BK) < Kz;
        float4 a0, a1, b0, b1;
        if (more) {
            a0 = *(const float4*)(Aptr + k0 + BK);
            a1 = *(const float4*)(Aptr + 64 * Kz + k0 + BK);
            b0 = *(const float4*)(Wptr + k0 + BK);
            b1 = *(const float4*)(Wptr + 64 * Kz + k0 + BK);
        }

        #pragma unroll
        for (int ks = 0; ks < 2; ks++) {
            int ko = ks * 8;
            uint32_t afr[4][4], bfr[4][2];
            #pragma unroll
            for (int mt = 0; mt < 4; mt++) {
                const float* p = &As[s * BUF + (wm + mt * 16 + frow) * SLD + ko + fk];
                afr[mt][0] = __float_as_uint(p[0]);
                afr[mt][1] = __float_as_uint(p[8 * SLD]);
                afr[mt][2] = __float_as_uint(p[4]);
                afr[mt][3] = __float_as_uint(p[8 * SLD + 4]);
            }
            #pragma unroll
            for (int nt = 0; nt < 4; nt++) {
                const float* q = &Bs[s * BUF + (wn + nt * 8 + frow) * SLD + ko + fk];
                bfr[nt][0] = __float_as_uint(q[0]);
                bfr[nt][1] = __float_as_uint(q[4]);
            }
            #pragma unroll
            for (int mt = 0; mt < 4; mt++)
                #pragma unroll
                for (int nt = 0; nt < 4; nt++)
                    mma_tf32(acc[mt][nt], afr[mt], bfr[nt]);
        }

        if (more) { STAGE(s ^ 1, a0, a1, b0, b1) }
        __syncthreads();
        s ^= 1;
    }
    #undef STAGE

    #pragma unroll
    for (int mt = 0; mt < 4; mt++) {
        int row = bm + wm + mt * 16 + frow;
        #pragma unroll
        for (int nt = 0; nt < 4; nt++) {
            int col = bn + wn + nt * 8 + fk * 2;
            float vv[4];
            #pragma unroll
            for (int r = 0; r < 4; r++) {
                float v = acc[mt][nt][r];
                if (epi == 1)      v = 1.f / (1.f + __expf(-v));
                else if (epi == 2) v = 0.999900004999833f / (1.f + __expf(-v));
                vv[r] = v;
            }
            *(float2*)&C[(size_t)row * Nz + col]       = make_float2(vv[0], vv[1]);
            *(float2*)&C[(size_t)(row + 8) * Nz + col] = make_float2(vv[2], vv[3]);
        }
    }
}

// fused 4 projection GEMMs: blockIdx.z selects which
__global__ void __launch_bounds__(256, 2) proj_gemm()
{
    __shared__ __align__(16) float As[2 * 128 * SLD];
    __shared__ __align__(16) float Bs[2 * 128 * SLD];
    int which = blockIdx.z;
    const float* A = g_buf[which];
    const float* W = g_wr + (size_t)which * (Dz * Dz);
    float* C = g_buf[4 + which];
    int epi = (which == 0) ? 1 : (which == 3) ? 2 : 0;
    gemm_body(As, Bs, A, W, C, epi);
}

__global__ void __launch_bounds__(256, 2) out_gemm(float* __restrict__ out)
{
    __shared__ __align__(16) float As[2 * 128 * SLD];
    __shared__ __align__(16) float Bs[2 * 128 * SLD];
    gemm_body(As, Bs, g_buf[8], g_wr + (size_t)4 * (Dz * Dz), out, 0);
}

// ---------------------------------------------------------------------------
// bonus coefficients: g_bsum[b,t,h] = sum_i r[i] * exp(u[i]+k[i])
// ---------------------------------------------------------------------------
__global__ void __launch_bounds__(256) bonus_kernel(const float* __restrict__ u)
{
    int warp = (blockIdx.x * blockDim.x + threadIdx.x) >> 5;
    int lane = threadIdx.x & 31;
    if (warp >= Bz * Tz * Hz) return;
    int bt = warp / Hz;
    int h  = warp - bt * Hz;

    int base = bt * Dz + h * 64;
    float r0 = g_buf[4][base + lane];
    float r1 = g_buf[4][base + 32 + lane];
    float k0 = g_buf[5][base + lane];
    float k1 = g_buf[5][base + 32 + lane];
    float u0 = u[h * 64 + lane];
    float u1 = u[h * 64 + 32 + lane];

    float term = r0 * __expf(u0 + k0) + r1 * __expf(u1 + k1);
    #pragma unroll
    for (int off = 16; off > 0; off >>= 1)
        term += __shfl_xor_sync(0xffffffffu, term, off);
    if (lane == 0) g_bsum[warp] = term;
}

// ---------------------------------------------------------------------------
// Pass A: chunk-local scan, zero init. grid (NC-1, NBH), 128 threads.
// Whole chunk (k,e,v) preloaded to smem; 64 steps with NO barriers.
// Thread (j, half) owns state rows [half*32, half*32+32) of column j.
// ---------------------------------------------------------------------------
__global__ void __launch_bounds__(128) scanA_kernel()
{
    extern __shared__ __align__(16) float sm[];
    float* k_s = sm;            // [64*64]
    float* e_s = sm + 4096;
    float* v_s = sm + 8192;

    int tid  = threadIdx.x;
    int j    = tid & 63;
    int half = tid >> 6;
    int c  = blockIdx.x;
    int bh = blockIdx.y;
    int b = bh >> 4, h = bh & 15;

    int base0 = (b * Tz + c * CL) * Dz + h * 64;

    // preload chunk: 1024 float4 per array
    #pragma unroll
    for (int it = 0; it < 8; it++) {
        int f  = it * 128 + tid;
        int t  = f >> 4;
        int i4 = (f & 15) << 2;
        int ga = base0 + t * Dz + i4;
        int sa = t * 64 + i4;
        *(float4*)&k_s[sa] = *(const float4*)&g_buf[5][ga];
        *(float4*)&e_s[sa] = *(const float4*)&g_buf[7][ga];
        *(float4*)&v_s[sa] = *(const float4*)&g_buf[6][ga];
    }
    __syncthreads();

    float s[32];
    #pragma unroll
    for (int i = 0; i < 32; i++) s[i] = 0.f;

    for (int t = 0; t < CL; t++) {
        float vj = v_s[t * 64 + j];
        const float4* kp = (const float4*)&k_s[t * 64 + half * 32];
        const float4* ep = (const float4*)&e_s[t * 64 + half * 32];
        #pragma unroll
        for (int q = 0; q < 8; q++) {
            float4 kv = kp[q], ev = ep[q];
            s[q * 4 + 0] = ev.x * s[q * 4 + 0] + kv.x * vj;
            s[q * 4 + 1] = ev.y * s[q * 4 + 1] + kv.y * vj;
            s[q * 4 + 2] = ev.z * s[q * 4 + 2] + kv.z * vj;
            s[q * 4 + 3] = ev.w * s[q * 4 + 3] + kv.w * vj;
        }
    }

    int slot = (bh * NC + c) * DHz;
    #pragma unroll 8
    for (int ii = 0; ii < 32; ii++)
        g_state[(size_t)(slot + half * 32 + ii) * DHz + j] = s[ii];

    if (half == 0) {
        float w0 = 1.f, w1 = 1.f, w2 = 1.f, w3 = 1.f;
        #pragma unroll
        for (int t = 0; t < CL; t += 4) {
            w0 *= e_s[(t + 0) * 64 + j];
            w1 *= e_s[(t + 1) * 64 + j];
            w2 *= e_s[(t + 2) * 64 + j];
            w3 *= e_s[(t + 3) * 64 + j];
        }
        g_wprod[slot + j] = (w0 * w1) * (w2 * w3);
    }
}

// ---------------------------------------------------------------------------
// Pass B: sequential prefix over chunks. grid NBH, 128 threads (i-split).
// ---------------------------------------------------------------------------
__global__ void __launch_bounds__(128) scanB_kernel()
{
    __shared__ float s_w[64];
    int tid  = threadIdx.x;
    int j    = tid & 63;
    int half = tid >> 6;
    int bh = blockIdx.x;

    float R[32];
    #pragma unroll
    for (int i = 0; i < 32; i++) R[i] = 0.f;

    for (int c = 0; c < NC; c++) {
        int slot = (bh * NC + c) * DHz;
        if (c < NC - 1) {
            if (tid < 64) s_w[tid] = g_wprod[slot + tid];
            __syncthreads();
            #pragma unroll 8
            for (int ii = 0; ii < 32; ii++) {
                int i = half * 32 + ii;
                size_t a = (size_t)(slot + i) * DHz + j;
                float local = g_state[a];
                g_state[a] = R[ii];
                R[ii] = s_w[i] * R[ii] + local;
            }
            __syncthreads();
        } else {
            #pragma unroll 8
            for (int ii = 0; ii < 32; ii++)
                g_state[(size_t)(slot + half * 32 + ii) * DHz + j] = R[ii];
        }
    }
}

// ---------------------------------------------------------------------------
// Pass C: outputs. grid (NC, NBH), 128 threads, no per-step barriers.
// Partial o (per half) kept in smem; combined after one sync.
// ---------------------------------------------------------------------------
__global__ void __launch_bounds__(128) scanC_kernel()
{
    extern __shared__ __align__(16) float sm[];
    float* k_s = sm;             // [4096]
    float* e_s = sm + 4096;
    float* v_s = sm + 8192;
    float* r_s = sm + 12288;
    float* op  = sm + 16384;     // [2][4096]
    float* bs_s = sm + 24576;    // [64]

    int tid  = threadIdx.x;
    int j    = tid & 63;
    int half = tid >> 6;
    int c  = blockIdx.x;
    int bh = blockIdx.y;
    int b = bh >> 4, h = bh & 15;

    int base0 = (b * Tz + c * CL) * Dz + h * 64;
    int bbase = (b * Tz + c * CL) * Hz + h;

    #pragma unroll
    for (int it = 0; it < 8; it++) {
        int f  = it * 128 + tid;
        int t  = f >> 4;
        int i4 = (f & 15) << 2;
        int ga = base0 + t * Dz + i4;
        int sa = t * 64 + i4;
        *(float4*)&k_s[sa] = *(const float4*)&g_buf[5][ga];
        *(float4*)&e_s[sa] = *(const float4*)&g_buf[7][ga];
        *(float4*)&v_s[sa] = *(const float4*)&g_buf[6][ga];
        *(float4*)&r_s[sa] = *(const float4*)&g_buf[4][ga];
    }
    if (tid < 64) bs_s[tid] = g_bsum[bbase + tid * Hz];

    float s[32];
    {
        int slot = (bh * NC + c) * DHz;
        #pragma unroll 8
        for (int ii = 0; ii < 32; ii++)
            s[ii] = g_state[(size_t)(slot + half * 32 + ii) * DHz + j];
    }
    __syncthreads();

    float* myop = op + half * 4096;
    for (int t = 0; t < CL; t++) {
        float vj = v_s[t * 64 + j];
        const float4* rp = (const float4*)&r_s[t * 64 + half * 32];
        const float4* kp = (const float4*)&k_s[t * 64 + half * 32];
        const float4* ep = (const float4*)&e_s[t * 64 + half * 32];
        float o0 = 0.f, o1 = 0.f, o2 = 0.f, o3 = 0.f;
        #pragma unroll
        for (int q = 0; q < 8; q++) {
            float4 rv = rp[q], kv = kp[q], ev = ep[q];
            o0 += rv.x * s[q * 4 + 0]; s[q * 4 + 0] = ev.x * s[q * 4 + 0] + kv.x * vj;
            o1 += rv.y * s[q * 4 + 1]; s[q * 4 + 1] = ev.y * s[q * 4 + 1] + kv.y * vj;
            o2 += rv.z * s[q * 4 + 2]; s[q * 4 + 2] = ev.z * s[q * 4 + 2] + kv.z * vj;
            o3 += rv.w * s[q * 4 + 3]; s[q * 4 + 3] = ev.w * s[q * 4 + 3] + kv.w * vj;
        }
        myop[t * 64 + j] = ((o0 + o1) + (o2 + o3));
    }
    __syncthreads();

    // combine halves + bonus, write out (coalesced)
    float* __restrict__ go = g_buf[8];
    #pragma unroll
    for (int it = 0; it < 32; it++) {
        int f  = it * 128 + tid;
        int t  = f >> 6;
        int jj = f & 63;
        float o = op[f] + op[4096 + f] + bs_s[t] * v_s[f];
        go[base0 + t * Dz + jj] = o;
    }
}

// ---------------------------------------------------------------------------
// GroupNorm + r-multiply; outputs tf32-rounded (feeds final GEMM only)
// ---------------------------------------------------------------------------
__global__ void __launch_bounds__(256) gnorm_kernel(const float* __restrict__ ln_w,
                                                    const float* __restrict__ ln_b)
{
    int warp = (blockIdx.x * blockDim.x + threadIdx.x) >> 5;
    int lane = threadIdx.x & 31;
    if (warp >= Bz * Tz * Hz) return;

    int base = warp * 64;
    float a0 = g_buf[8][base + lane];
    float a1 = g_buf[8][base + 32 + lane];

    float sum = a0 + a1;
    float sq  = a0 * a0 + a1 * a1;
    #pragma unroll
    for (int off = 16; off > 0; off >>= 1) {
        sum += __shfl_xor_sync(0xffffffffu, sum, off);
        sq  += __shfl_xor_sync(0xffffffffu, sq,  off);
    }
    float mean = sum * (1.f / 64.f);
    float var  = sq * (1.f / 64.f) - mean * mean;
    float rs   = rsqrtf(var + 1e-5f);

    float r0 = g_buf[4][base + lane];
    float r1 = g_buf[4][base + 32 + lane];
    g_buf[8][base + lane] =
        to_tf32(((a0 - mean) * rs * ln_w[lane] + ln_b[lane]) * r0);
    g_buf[8][base + 32 + lane] =
        to_tf32(((a1 - mean) * rs * ln_w[lane + 32] + ln_b[lane + 32]) * r1);
}

// ---------------------------------------------------------------------------
extern "C" void kernel_launch(void* const* d_in, const int* in_sizes, int n_in,
                              void* d_out, int out_size)
{
    const float* x    = (const float*)d_in[0];
    const float* W_r  = (const float*)d_in[1];
    const float* W_k  = (const float*)d_in[2];
    const float* W_v  = (const float*)d_in[3];
    const float* W_w  = (const float*)d_in[4];
    const float* W_o  = (const float*)d_in[5];
    const float* u    = (const float*)d_in[6];
    const float* tm_r = (const float*)d_in[7];
    const float* tm_k = (const float*)d_in[8];
    const float* tm_v = (const float*)d_in[9];
    const float* tm_w = (const float*)d_in[10];
    const float* ln_w = (const float*)d_in[11];
    const float* ln_b = (const float*)d_in[12];
    float* out = (float*)d_out;

    cudaFuncSetAttribute(scanA_kernel,
        cudaFuncAttributeMaxDynamicSharedMemorySize, 12288 * 4);
    cudaFuncSetAttribute(scanC_kernel,
        cudaFuncAttributeMaxDynamicSharedMemorySize, 24640 * 4);

    roundw_kernel<<<5120, 256>>>(
        (const float4*)W_r, (const float4*)W_k, (const float4*)W_v,
        (const float4*)W_w, (const float4*)W_o);

    mix_kernel<<<(MD / 4) / 256, 256>>>(
        (const float4*)x, (const float4*)tm_r, (const float4*)tm_k,
        (const float4*)tm_v, (const float4*)tm_w);

    proj_gemm<<<dim3(Nz / 128, Mz / 128, 4), 256>>>();

    bonus_kernel<<<(Bz * Tz * Hz) / 8, 256>>>(u);

    scanA_kernel<<<dim3(NC - 1, NBH), 128, 12288 * 4>>>();
    scanB_kernel<<<NBH, 128>>>();
    scanC_kernel<<<dim3(NC, NBH), 128, 24640 * 4>>>();

    gnorm_kernel<<<(Bz * Tz * Hz) / 8, 256>>>(ln_w, ln_b);

    out_gemm<<<dim3(Nz / 128, Mz / 128), 256>>>(out);
}

// round 6
// speedup vs baseline: 3.0439x; 1.0187x over previous
#include <cuda_runtime.h>
#include <cstdint>

#define Bz 4
#define Tz 1024
#define Dz 1024
#define Hz 16
#define DHz 64
#define Mz (Bz*Tz)        // 4096
#define Kz Dz
#define Nz Dz
#define MD (Mz*Dz)        // 4,194,304
#define NBH (Bz*Hz)       // 64
#define CL 64             // chunk length
#define NC (Tz/CL)        // 16 chunks

// scratch: 0..3 = xr,xk,xv,xw (tf32-rounded) ; 4=r ; 5=k ; 6=v ; 7=exp(w) ; 8=o
__device__ float g_buf[9][MD];
__device__ float g_wr[5 * Dz * Dz];               // tf32-rounded weights
__device__ float g_state[NBH * NC * DHz * DHz];   // chunk states
__device__ float g_wprod[NBH * NC * DHz];         // per-chunk decay products
__device__ float g_bsum[Bz * Tz * Hz];            // bonus coefficients

__device__ __forceinline__ float to_tf32(float x)
{
    uint32_t d;
    asm("cvt.rna.tf32.f32 %0, %1;" : "=r"(d) : "f"(x));
    return __uint_as_float(d);
}

__device__ __forceinline__ uint32_t smem_to_u32(const void* p) {
    uint32_t a;
    asm("{ .reg .u64 t; cvta.to.shared.u64 t, %1; cvt.u32.u64 %0, t; }"
        : "=r"(a) : "l"(p));
    return a;
}
__device__ __forceinline__ void cp16(uint32_t dst, const void* src) {
    asm volatile("cp.async.cg.shared.global [%0], [%1], 16;"
                 :: "r"(dst), "l"(src));
}
__device__ __forceinline__ void cp_commit() {
    asm volatile("cp.async.commit_group;" ::: "memory");
}

// ---------------------------------------------------------------------------
// round the 5 weight matrices to tf32 into g_wr
// ---------------------------------------------------------------------------
__global__ void __launch_bounds__(256) roundw_kernel(
    const float4* __restrict__ a, const float4* __restrict__ b,
    const float4* __restrict__ c, const float4* __restrict__ d,
    const float4* __restrict__ e)
{
    int idx = blockIdx.x * 256 + threadIdx.x;
    int which = idx >> 18;
    int off = idx & 262143;
    const float4* src = which == 0 ? a : which == 1 ? b : which == 2 ? c
                       : which == 3 ? d : e;
    float4 v = src[off];
    v.x = to_tf32(v.x); v.y = to_tf32(v.y); v.z = to_tf32(v.z); v.w = to_tf32(v.w);
    reinterpret_cast<float4*>(g_wr)[idx] = v;
}

// ---------------------------------------------------------------------------
// token-shift mix, outputs tf32-rounded (GEMM inputs only)
// ---------------------------------------------------------------------------
__global__ void __launch_bounds__(256) mix_kernel(
    const float4* __restrict__ x,
    const float4* __restrict__ tmr, const float4* __restrict__ tmk,
    const float4* __restrict__ tmv, const float4* __restrict__ tmw)
{
    int idx = blockIdx.x * blockDim.x + threadIdx.x;
    int m  = idx >> 8;
    int c4 = idx & 255;
    int t  = m & (Tz - 1);

    float4 xc = x[idx];
    float4 xp = make_float4(0.f, 0.f, 0.f, 0.f);
    if (t != 0) xp = x[idx - 256];

    float4 w, o;
    #define DO_MIX(TMV, DSTI)                                   \
        w = TMV[c4];                                            \
        o.x = to_tf32(w.x * xc.x + (1.f - w.x) * xp.x);         \
        o.y = to_tf32(w.y * xc.y + (1.f - w.y) * xp.y);         \
        o.z = to_tf32(w.z * xc.z + (1.f - w.z) * xp.z);         \
        o.w = to_tf32(w.w * xc.w + (1.f - w.w) * xp.w);         \
        reinterpret_cast<float4*>(g_buf[DSTI])[idx] = o;
    DO_MIX(tmr, 0)
    DO_MIX(tmk, 1)
    DO_MIX(tmv, 2)
    DO_MIX(tmw, 3)
    #undef DO_MIX
}

// ---------------------------------------------------------------------------
// tf32 mma.sync GEMM: C[m][n] = sum_k A[m][k] * W[n][k]
// CTA tile 128(M) x 256(N), BK=32, 8 warps (2m x 4n), warp tile 64x64.
// cp.async double-buffered staging; fragments via conflict-free LDS.
// epi: 0 identity, 1 sigmoid, 2 sigmoid * exp(-1e-4)
// ---------------------------------------------------------------------------
__device__ __forceinline__ void mma_tf32(float c[4], const uint32_t a[4],
                                         const uint32_t b[2])
{
    asm volatile(
        "mma.sync.aligned.m16n8k8.row.col.f32.tf32.tf32.f32 "
        "{%0,%1,%2,%3}, {%4,%5,%6,%7}, {%8,%9}, {%0,%1,%2,%3};"
        : "+f"(c[0]), "+f"(c[1]), "+f"(c[2]), "+f"(c[3])
        : "r"(a[0]), "r"(a[1]), "r"(a[2]), "r"(a[3]),
          "r"(b[0]), "r"(b[1]));
}

#define GBK 32
#define GSLD 36                    // GBK + 4 pad (conflict-free fragment LDS)
#define ABUF (128 * GSLD)          // floats per A buffer
#define BBUF (256 * GSLD)          // floats per B buffer
#define GSM_BYTES ((2 * ABUF + 2 * BBUF) * 4)   // 110592 B

__device__ __forceinline__ void gemm_stage(
    const float* __restrict__ A, const float* __restrict__ W,
    int bm, int bn, int c, uint32_t sA, uint32_t sB, int tid)
{
    const char* ap = (const char*)(A + (size_t)bm * Kz + c * GBK);
    #pragma unroll
    for (int i = 0; i < 4; i++) {             // A: 128 rows x 8 granules
        int g = i * 256 + tid;
        int r = g >> 3;
        int gc = (g & 7) << 4;
        cp16(sA + r * (GSLD * 4) + gc, ap + (size_t)r * 4096 + gc);
    }
    const char* bp = (const char*)(W + (size_t)bn * Kz + c * GBK);
    #pragma unroll
    for (int i = 0; i < 8; i++) {             // B: 256 rows x 8 granules
        int g = i * 256 + tid;
        int r = g >> 3;
        int gc = (g & 7) << 4;
        cp16(sB + r * (GSLD * 4) + gc, bp + (size_t)r * 4096 + gc);
    }
}

__device__ __forceinline__ void gemm_body(
    const float* __restrict__ A, const float* __restrict__ W,
    float* __restrict__ C, int epi)
{
    extern __shared__ __align__(16) float sm[];
    float* As = sm;                    // [2][ABUF]
    float* Bs = sm + 2 * ABUF;         // [2][BBUF]
    uint32_t a32 = smem_to_u32(As);
    uint32_t b32 = smem_to_u32(Bs);

    int tid  = threadIdx.x;
    int lane = tid & 31;
    int wid  = tid >> 5;
    int bm = blockIdx.y * 128;
    int bn = blockIdx.x * 256;

    int wm = (wid >> 2) * 64;          // 0 / 64
    int wn = (wid & 3) * 64;           // 0 / 64 / 128 / 192
    int frow = lane >> 2;
    int fk   = lane & 3;

    float acc[4][8][4];
    #pragma unroll
    for (int i = 0; i < 4; i++)
        #pragma unroll
        for (int j = 0; j < 8; j++)
            #pragma unroll
            for (int r = 0; r < 4; r++) acc[i][j][r] = 0.f;

    gemm_stage(A, W, bm, bn, 0, a32, b32, tid);
    cp_commit();

    const int NIT = Kz / GBK;          // 32
    for (int c = 0; c < NIT; c++) {
        int buf = c & 1;
        if (c + 1 < NIT) {
            int nb = (c + 1) & 1;
            gemm_stage(A, W, bm, bn, c + 1,
                       a32 + nb * (ABUF * 4), b32 + nb * (BBUF * 4), tid);
            cp_commit();
            asm volatile("cp.async.wait_group 1;" ::: "memory");
        } else {
            asm volatile("cp.async.wait_group 0;" ::: "memory");
        }
        __syncthreads();

        const float* a_s = As + buf * ABUF;
        const float* b_s = Bs + buf * BBUF;
        #pragma unroll
        for (int ks = 0; ks < 4; ks++) {
            int ko = ks * 8;
            uint32_t afr[4][4], bfr[8][2];
            #pragma unroll
            for (int mt = 0; mt < 4; mt++) {
                const float* p = &a_s[(wm + mt * 16 + frow) * GSLD + ko + fk];
                afr[mt][0] = __float_as_uint(p[0]);
                afr[mt][1] = __float_as_uint(p[8 * GSLD]);
                afr[mt][2] = __float_as_uint(p[4]);
                afr[mt][3] = __float_as_uint(p[8 * GSLD + 4]);
            }
            #pragma unroll
            for (int nt = 0; nt < 8; nt++) {
                const float* q = &b_s[(wn + nt * 8 + frow) * GSLD + ko + fk];
                bfr[nt][0] = __float_as_uint(q[0]);
                bfr[nt][1] = __float_as_uint(q[4]);
            }
            #pragma unroll
            for (int mt = 0; mt < 4; mt++)
                #pragma unroll
                for (int nt = 0; nt < 8; nt++)
                    mma_tf32(acc[mt][nt], afr[mt], bfr[nt]);
        }
        __syncthreads();
    }

    #pragma unroll
    for (int mt = 0; mt < 4; mt++) {
        int row = bm + wm + mt * 16 + frow;
        #pragma unroll
        for (int nt = 0; nt < 8; nt++) {
            int col = bn + wn + nt * 8 + fk * 2;
            float vv[4];
            #pragma unroll
            for (int r = 0; r < 4; r++) {
                float v = acc[mt][nt][r];
                if (epi == 1)      v = 1.f / (1.f + __expf(-v));
                else if (epi == 2) v = 0.999900004999833f / (1.f + __expf(-v));
                vv[r] = v;
            }
            *(float2*)&C[(size_t)row * Nz + col]       = make_float2(vv[0], vv[1]);
            *(float2*)&C[(size_t)(row + 8) * Nz + col] = make_float2(vv[2], vv[3]);
        }
    }
}

__global__ void __launch_bounds__(256) proj_gemm()
{
    int which = blockIdx.z;
    int epi = (which == 0) ? 1 : (which == 3) ? 2 : 0;
    gemm_body(g_buf[which], g_wr + (size_t)which * (Dz * Dz),
              g_buf[4 + which], epi);
}

__global__ void __launch_bounds__(256) out_gemm(float* __restrict__ out)
{
    gemm_body(g_buf[8], g_wr + (size_t)4 * (Dz * Dz), out, 0);
}

// ---------------------------------------------------------------------------
// bonus coefficients: g_bsum[b,t,h] = sum_i r[i] * exp(u[i]+k[i])
// ---------------------------------------------------------------------------
__global__ void __launch_bounds__(256) bonus_kernel(const float* __restrict__ u)
{
    int warp = (blockIdx.x * blockDim.x + threadIdx.x) >> 5;
    int lane = threadIdx.x & 31;
    if (warp >= Bz * Tz * Hz) return;
    int bt = warp / Hz;
    int h  = warp - bt * Hz;

    int base = bt * Dz + h * 64;
    float r0 = g_buf[4][base + lane];
    float r1 = g_buf[4][base + 32 + lane];
    float k0 = g_buf[5][base + lane];
    float k1 = g_buf[5][base + 32 + lane];
    float u0 = u[h * 64 + lane];
    float u1 = u[h * 64 + 32 + lane];

    float term = r0 * __expf(u0 + k0) + r1 * __expf(u1 + k1);
    #pragma unroll
    for (int off = 16; off > 0; off >>= 1)
        term += __shfl_xor_sync(0xffffffffu, term, off);
    if (lane == 0) g_bsum[warp] = term;
}

// ---------------------------------------------------------------------------
// Pass A: chunk-local scan, zero init. grid (NC-1, NBH), 128 threads.
// ---------------------------------------------------------------------------
__global__ void __launch_bounds__(128) scanA_kernel()
{
    extern __shared__ __align__(16) float sm[];
    float* k_s = sm;
    float* e_s = sm + 4096;
    float* v_s = sm + 8192;

    int tid  = threadIdx.x;
    int j    = tid & 63;
    int half = tid >> 6;
    int c  = blockIdx.x;
    int bh = blockIdx.y;
    int b = bh >> 4, h = bh & 15;

    int base0 = (b * Tz + c * CL) * Dz + h * 64;

    #pragma unroll
    for (int it = 0; it < 8; it++) {
        int f  = it * 128 + tid;
        int t  = f >> 4;
        int i4 = (f & 15) << 2;
        int ga = base0 + t * Dz + i4;
        int sa = t * 64 + i4;
        *(float4*)&k_s[sa] = *(const float4*)&g_buf[5][ga];
        *(float4*)&e_s[sa] = *(const float4*)&g_buf[7][ga];
        *(float4*)&v_s[sa] = *(const float4*)&g_buf[6][ga];
    }
    __syncthreads();

    float s[32];
    #pragma unroll
    for (int i = 0; i < 32; i++) s[i] = 0.f;

    for (int t = 0; t < CL; t++) {
        float vj = v_s[t * 64 + j];
        const float4* kp = (const float4*)&k_s[t * 64 + half * 32];
        const float4* ep = (const float4*)&e_s[t * 64 + half * 32];
        #pragma unroll
        for (int q = 0; q < 8; q++) {
            float4 kv = kp[q], ev = ep[q];
            s[q * 4 + 0] = ev.x * s[q * 4 + 0] + kv.x * vj;
            s[q * 4 + 1] = ev.y * s[q * 4 + 1] + kv.y * vj;
            s[q * 4 + 2] = ev.z * s[q * 4 + 2] + kv.z * vj;
            s[q * 4 + 3] = ev.w * s[q * 4 + 3] + kv.w * vj;
        }
    }

    int slot = (bh * NC + c) * DHz;
    #pragma unroll 8
    for (int ii = 0; ii < 32; ii++)
        g_state[(size_t)(slot + half * 32 + ii) * DHz + j] = s[ii];

    if (half == 0) {
        float w0 = 1.f, w1 = 1.f, w2 = 1.f, w3 = 1.f;
        #pragma unroll
        for (int t = 0; t < CL; t += 4) {
            w0 *= e_s[(t + 0) * 64 + j];
            w1 *= e_s[(t + 1) * 64 + j];
            w2 *= e_s[(t + 2) * 64 + j];
            w3 *= e_s[(t + 3) * 64 + j];
        }
        g_wprod[slot + j] = (w0 * w1) * (w2 * w3);
    }
}

// ---------------------------------------------------------------------------
// Pass B: sequential prefix over chunks. grid NBH, 128 threads (i-split).
// ---------------------------------------------------------------------------
__global__ void __launch_bounds__(128) scanB_kernel()
{
    __shared__ float s_w[64];
    int tid  = threadIdx.x;
    int j    = tid & 63;
    int half = tid >> 6;
    int bh = blockIdx.x;

    float R[32];
    #pragma unroll
    for (int i = 0; i < 32; i++) R[i] = 0.f;

    for (int c = 0; c < NC; c++) {
        int slot = (bh * NC + c) * DHz;
        if (c < NC - 1) {
            if (tid < 64) s_w[tid] = g_wprod[slot + tid];
            __syncthreads();
            #pragma unroll 8
            for (int ii = 0; ii < 32; ii++) {
                int i = half * 32 + ii;
                size_t a = (size_t)(slot + i) * DHz + j;
                float local = g_state[a];
                g_state[a] = R[ii];
                R[ii] = s_w[i] * R[ii] + local;
            }
            __syncthreads();
        } else {
            #pragma unroll 8
            for (int ii = 0; ii < 32; ii++)
                g_state[(size_t)(slot + half * 32 + ii) * DHz + j] = R[ii];
        }
    }
}

// ---------------------------------------------------------------------------
// Pass C: outputs. grid (NC, NBH), 128 threads, no per-step barriers.
// ---------------------------------------------------------------------------
__global__ void __launch_bounds__(128) scanC_kernel()
{
    extern __shared__ __align__(16) float sm[];
    float* k_s = sm;
    float* e_s = sm + 4096;
    float* v_s = sm + 8192;
    float* r_s = sm + 12288;
    float* op  = sm + 16384;
    float* bs_s = sm + 24576;

    int tid  = threadIdx.x;
    int j    = tid & 63;
    int half = tid >> 6;
    int c  = blockIdx.x;
    int bh = blockIdx.y;
    int b = bh >> 4, h = bh & 15;

    int base0 = (b * Tz + c * CL) * Dz + h * 64;
    int bbase = (b * Tz + c * CL) * Hz + h;

    #pragma unroll
    for (int it = 0; it < 8; it++) {
        int f  = it * 128 + tid;
        int t  = f >> 4;
        int i4 = (f & 15) << 2;
        int ga = base0 + t * Dz + i4;
        int sa = t * 64 + i4;
        *(float4*)&k_s[sa] = *(const float4*)&g_buf[5][ga];
        *(float4*)&e_s[sa] = *(const float4*)&g_buf[7][ga];
        *(float4*)&v_s[sa] = *(const float4*)&g_buf[6][ga];
        *(float4*)&r_s[sa] = *(const float4*)&g_buf[4][ga];
    }
    if (tid < 64) bs_s[tid] = g_bsum[bbase + tid * Hz];

    float s[32];
    {
        int slot = (bh * NC + c) * DHz;
        #pragma unroll 8
        for (int ii = 0; ii < 32; ii++)
            s[ii] = g_state[(size_t)(slot + half * 32 + ii) * DHz + j];
    }
    __syncthreads();

    float* myop = op + half * 4096;
    for (int t = 0; t < CL; t++) {
        float vj = v_s[t * 64 + j];
        const float4* rp = (const float4*)&r_s[t * 64 + half * 32];
        const float4* kp = (const float4*)&k_s[t * 64 + half * 32];
        const float4* ep = (const float4*)&e_s[t * 64 + half * 32];
        float o0 = 0.f, o1 = 0.f, o2 = 0.f, o3 = 0.f;
        #pragma unroll
        for (int q = 0; q < 8; q++) {
            float4 rv = rp[q], kv = kp[q], ev = ep[q];
            o0 += rv.x * s[q * 4 + 0]; s[q * 4 + 0] = ev.x * s[q * 4 + 0] + kv.x * vj;
            o1 += rv.y * s[q * 4 + 1]; s[q * 4 + 1] = ev.y * s[q * 4 + 1] + kv.y * vj;
            o2 += rv.z * s[q * 4 + 2]; s[q * 4 + 2] = ev.z * s[q * 4 + 2] + kv.z * vj;
            o3 += rv.w * s[q * 4 + 3]; s[q * 4 + 3] = ev.w * s[q * 4 + 3] + kv.w * vj;
        }
        myop[t * 64 + j] = ((o0 + o1) + (o2 + o3));
    }
    __syncthreads();

    float* __restrict__ go = g_buf[8];
    #pragma unroll
    for (int it = 0; it < 32; it++) {
        int f  = it * 128 + tid;
        int t  = f >> 6;
        int jj = f & 63;
        float o = op[f] + op[4096 + f] + bs_s[t] * v_s[f];
        go[base0 + t * Dz + jj] = o;
    }
}

// ---------------------------------------------------------------------------
// GroupNorm + r-multiply; outputs tf32-rounded (feeds final GEMM only)
// ---------------------------------------------------------------------------
__global__ void __launch_bounds__(256) gnorm_kernel(const float* __restrict__ ln_w,
                                                    const float* __restrict__ ln_b)
{
    int warp = (blockIdx.x * blockDim.x + threadIdx.x) >> 5;
    int lane = threadIdx.x & 31;
    if (warp >= Bz * Tz * Hz) return;

    int base = warp * 64;
    float a0 = g_buf[8][base + lane];
    float a1 = g_buf[8][base + 32 + lane];

    float sum = a0 + a1;
    float sq  = a0 * a0 + a1 * a1;
    #pragma unroll
    for (int off = 16; off > 0; off >>= 1) {
        sum += __shfl_xor_sync(0xffffffffu, sum, off);
        sq  += __shfl_xor_sync(0xffffffffu, sq,  off);
    }
    float mean = sum * (1.f / 64.f);
    float var  = sq * (1.f / 64.f) - mean * mean;
    float rs   = rsqrtf(var + 1e-5f);

    float r0 = g_buf[4][base + lane];
    float r1 = g_buf[4][base + 32 + lane];
    g_buf[8][base + lane] =
        to_tf32(((a0 - mean) * rs * ln_w[lane] + ln_b[lane]) * r0);
    g_buf[8][base + 32 + lane] =
        to_tf32(((a1 - mean) * rs * ln_w[lane + 32] + ln_b[lane + 32]) * r1);
}

// ---------------------------------------------------------------------------
extern "C" void kernel_launch(void* const* d_in, const int* in_sizes, int n_in,
                              void* d_out, int out_size)
{
    const float* x    = (const float*)d_in[0];
    const float* W_r  = (const float*)d_in[1];
    const float* W_k  = (const float*)d_in[2];
    const float* W_v  = (const float*)d_in[3];
    const float* W_w  = (const float*)d_in[4];
    const float* W_o  = (const float*)d_in[5];
    const float* u    = (const float*)d_in[6];
    const float* tm_r = (const float*)d_in[7];
    const float* tm_k = (const float*)d_in[8];
    const float* tm_v = (const float*)d_in[9];
    const float* tm_w = (const float*)d_in[10];
    const float* ln_w = (const float*)d_in[11];
    const float* ln_b = (const float*)d_in[12];
    float* out = (float*)d_out;

    cudaFuncSetAttribute(scanA_kernel,
        cudaFuncAttributeMaxDynamicSharedMemorySize, 12288 * 4);
    cudaFuncSetAttribute(scanC_kernel,
        cudaFuncAttributeMaxDynamicSharedMemorySize, 24640 * 4);
    cudaFuncSetAttribute(proj_gemm,
        cudaFuncAttributeMaxDynamicSharedMemorySize, GSM_BYTES);
    cudaFuncSetAttribute(out_gemm,
        cudaFuncAttributeMaxDynamicSharedMemorySize, GSM_BYTES);

    roundw_kernel<<<5120, 256>>>(
        (const float4*)W_r, (const float4*)W_k, (const float4*)W_v,
        (const float4*)W_w, (const float4*)W_o);

    mix_kernel<<<(MD / 4) / 256, 256>>>(
        (const float4*)x, (const float4*)tm_r, (const float4*)tm_k,
        (const float4*)tm_v, (const float4*)tm_w);

    proj_gemm<<<dim3(Nz / 256, Mz / 128, 4), 256, GSM_BYTES>>>();

    bonus_kernel<<<(Bz * Tz * Hz) / 8, 256>>>(u);

    scanA_kernel<<<dim3(NC - 1, NBH), 128, 12288 * 4>>>();
    scanB_kernel<<<NBH, 128>>>();
    scanC_kernel<<<dim3(NC, NBH), 128, 24640 * 4>>>();

    gnorm_kernel<<<(Bz * Tz * Hz) / 8, 256>>>(ln_w, ln_b);

    out_gemm<<<dim3(Nz / 256, Mz / 128), 256, GSM_BYTES>>>(out);
}